// round 15
// baseline (speedup 1.0000x reference)
#include <cuda_runtime.h>
#include <cuda_fp16.h>
#include <cstdint>
#include <math.h>

#define Bb 2
#define Ss 2048
#define Dd 1024
#define Hh 16
#define HDIM 64
#define Mrows (Bb*Ss)   // 4096
#define QKVD (3*Dd)     // 3072

// ---------------------------------------------------------------------------
// Scratch
// ---------------------------------------------------------------------------
__device__ float g_cos[Ss * 32];
__device__ float g_sin[Ss * 32];
__device__ double g_invf[32];
__device__ __half g_hA[(size_t)Mrows * Dd];
__device__ __half g_hW[(size_t)QKVD * Dd];   // qkv weights fp16
__device__ __half g_hWp[(size_t)Dd * Dd];    // proj weights fp16
// head-major fp16 q/k/v for attention: [b*16+h][s][64]
__device__ __half g_qh[(size_t)Bb * Hh * Ss * HDIM];
__device__ __half g_kh[(size_t)Bb * Hh * Ss * HDIM];
__device__ __half g_vh[(size_t)Bb * Hh * Ss * HDIM];

// ---------------------------------------------------------------------------
// Helpers
// ---------------------------------------------------------------------------
__device__ __forceinline__ uint32_t smem_to_u32(const void* p) {
    uint32_t a;
    asm("{ .reg .u64 t; cvta.to.shared.u64 t, %1; cvt.u32.u64 %0, t; }"
        : "=r"(a) : "l"(p));
    return a;
}
__device__ __forceinline__ void ldsm_x4(uint32_t addr, uint32_t& r0, uint32_t& r1,
                                        uint32_t& r2, uint32_t& r3) {
    asm volatile("ldmatrix.sync.aligned.m8n8.x4.shared.b16 {%0,%1,%2,%3}, [%4];"
                 : "=r"(r0), "=r"(r1), "=r"(r2), "=r"(r3) : "r"(addr));
}
__device__ __forceinline__ void ldsm_x4t(uint32_t addr, uint32_t& r0, uint32_t& r1,
                                         uint32_t& r2, uint32_t& r3) {
    asm volatile("ldmatrix.sync.aligned.m8n8.x4.trans.shared.b16 {%0,%1,%2,%3}, [%4];"
                 : "=r"(r0), "=r"(r1), "=r"(r2), "=r"(r3) : "r"(addr));
}
__device__ __forceinline__ void mma16816(float* c, const uint32_t* a, const uint32_t* b) {
    asm volatile("mma.sync.aligned.m16n8k16.row.col.f32.f16.f16.f32 "
                 "{%0,%1,%2,%3}, {%4,%5,%6,%7}, {%8,%9}, {%0,%1,%2,%3};"
                 : "+f"(c[0]), "+f"(c[1]), "+f"(c[2]), "+f"(c[3])
                 : "r"(a[0]), "r"(a[1]), "r"(a[2]), "r"(a[3]), "r"(b[0]), "r"(b[1]));
}
#define CP_ASYNC16(sa, ga) \
    asm volatile("cp.async.cg.shared.global [%0], [%1], 16;" :: "r"(sa), "l"(ga))
#define CP_COMMIT() asm volatile("cp.async.commit_group;" ::: "memory")
#define CP_WAIT1()  asm volatile("cp.async.wait_group 1;" ::: "memory")
#define CP_WAIT0()  asm volatile("cp.async.wait_group 0;" ::: "memory")

__device__ __forceinline__ uint32_t packf2h(float a, float b) {
    __half2 h = __floats2half2_rn(a, b);
    return *(uint32_t*)&h;
}
__device__ __forceinline__ uint32_t packh(__half a, __half b) {
    return ((uint32_t)__half_as_ushort(b) << 16) | (uint32_t)__half_as_ushort(a);
}

// ---------------------------------------------------------------------------
// Fused RMSNorm + fp16 convert: x -> g_hA
// ---------------------------------------------------------------------------
__global__ void __launch_bounds__(256)
rmsnorm_h_kernel(const float* __restrict__ x, const float* __restrict__ w) {
    const int row = blockIdx.x;
    const float4* xr = (const float4*)(x + (size_t)row * Dd);
    const float4 v = xr[threadIdx.x];
    float ss = v.x * v.x + v.y * v.y + v.z * v.z + v.w * v.w;
    __shared__ float red[8];
    #pragma unroll
    for (int o = 16; o > 0; o >>= 1) ss += __shfl_xor_sync(0xffffffffu, ss, o);
    const int wid = threadIdx.x >> 5, lid = threadIdx.x & 31;
    if (lid == 0) red[wid] = ss;
    __syncthreads();
    if (wid == 0) {
        ss = (lid < 8) ? red[lid] : 0.f;
        #pragma unroll
        for (int o = 4; o > 0; o >>= 1) ss += __shfl_xor_sync(0xffffffffu, ss, o);
        if (lid == 0) red[0] = ss;
    }
    __syncthreads();
    const float inv = rsqrtf(red[0] * (1.0f / Dd) + 1e-6f);
    const float4 wv = ((const float4*)w)[threadIdx.x];
    const size_t o4 = (size_t)row * (Dd / 4) + threadIdx.x;
    ((uint2*)g_hA)[o4] = make_uint2(
        packh(__float2half_rn(v.x * inv * wv.x), __float2half_rn(v.y * inv * wv.y)),
        packh(__float2half_rn(v.z * inv * wv.z), __float2half_rn(v.w * inv * wv.w)));
}

// ---------------------------------------------------------------------------
// RoPE tables: (1) inv_freq via fp64 pow, 32 threads only
//              (2) cos/sin via fp64 range reduction + fp32 sincosf
// ---------------------------------------------------------------------------
__global__ void rope_invf_kernel() {
    const int i = threadIdx.x;  // 0..31
    g_invf[i] = pow(10000.0, -((double)(2 * i)) / 64.0);
}
__global__ void __launch_bounds__(256)
rope_table_kernel() {
    const int idx = blockIdx.x * blockDim.x + threadIdx.x;  // 0..65535
    const int t = idx >> 5, i = idx & 31;
    const double TWO_PI = 6.283185307179586476925286766559;
    double a = (double)t * g_invf[i];
    double r = a - rint(a * (1.0 / TWO_PI)) * TWO_PI;   // |r| <= pi
    float c, s;
    sincosf((float)r, &s, &c);
    g_cos[t * 32 + i] = c;
    g_sin[t * 32 + i] = s;
}

// ---------------------------------------------------------------------------
// fp32 -> fp16 (weights)
// ---------------------------------------------------------------------------
__global__ void split_f16_hi_kernel(const float4* __restrict__ src,
                                    uint2* __restrict__ hi, int n4) {
    int i = blockIdx.x * blockDim.x + threadIdx.x;
    if (i >= n4) return;
    float4 v = src[i];
    hi[i] = make_uint2(packh(__float2half_rn(v.x), __float2half_rn(v.y)),
                       packh(__float2half_rn(v.z), __float2half_rn(v.w)));
}

// ---------------------------------------------------------------------------
// Single-pass fp16 GEMM via mma.sync: C = A * W^T + bias
//   CTA 128x128, 8 warps (4M x 2N), KC=64, 3-stage cp.async pipeline.
//   mode 0: fp32 C (+bias).  mode 1: QKV epilogue (bias+RoPE+fp16 head-major).
// ---------------------------------------------------------------------------
#define PADB  144                    // 64 halfs (128 B) + 16 pad
#define TILEB (128 * PADB)           // 18432
#define STAGEB (2 * TILEB)           // 36864: A, W
#define NSTAGE 3
#define GSMEM (NSTAGE * STAGEB)      // 110592

__global__ void __launch_bounds__(256)
gemm_f16(const __half* __restrict__ Ahi, const __half* __restrict__ Whi,
         const float* __restrict__ bias, float* __restrict__ C,
         int M, int N, int K, int mode) {
    extern __shared__ char smem[];
    const uint32_t sb = smem_to_u32(smem);
    const int tid = threadIdx.x, lane = tid & 31, w = tid >> 5;
    const int bm = blockIdx.y * 128, bn = blockIdx.x * 128;
    const int wm = (w >> 1) * 32, wn = (w & 1) * 64;

    auto load_stage = [&](int s, int k0) {
        const uint32_t st = sb + s * STAGEB;
        #pragma unroll
        for (int t = 0; t < 2; t++) {
            const __half* src = (t == 0 ? Ahi : Whi)
                                + (size_t)(t == 0 ? bm : bn) * K + k0;
            const uint32_t tb = st + t * TILEB;
            #pragma unroll
            for (int j = 0; j < 4; j++) {
                const int c = tid + j * 256;
                const int row = c >> 3, c16 = c & 7;
                CP_ASYNC16(tb + row * PADB + c16 * 16,
                           src + (size_t)row * K + c16 * 8);
            }
        }
    };

    float acc[2][8][4];
    #pragma unroll
    for (int mi = 0; mi < 2; mi++)
        #pragma unroll
        for (int nj = 0; nj < 8; nj++)
            #pragma unroll
            for (int r = 0; r < 4; r++) acc[mi][nj][r] = 0.f;

    load_stage(0, 0);  CP_COMMIT();
    load_stage(1, 64); CP_COMMIT();

    const int nch = K >> 6;          // chunks of 64
    const int sel = lane >> 3;
    const int asub = (sel & 1) * 8, ak8 = (sel >> 1) * 8;
    const int nsub = (sel >> 1) * 8, bk8 = (sel & 1) * 8;

    for (int cidx = 0; cidx < nch; cidx++) {
        CP_WAIT1();
        __syncthreads();
        if (cidx + 2 < nch) load_stage((cidx + 2) % NSTAGE, (cidx + 2) * 64);
        CP_COMMIT();

        const uint32_t st = sb + (cidx % NSTAGE) * STAGEB;
        #pragma unroll
        for (int kk = 0; kk < 4; kk++) {
            const int ko = kk * 16;
            uint32_t ah[2][4], wh[8][2];
            #pragma unroll
            for (int mi = 0; mi < 2; mi++) {
                const uint32_t addr = st + (wm + mi * 16 + (lane & 7) + asub) * PADB
                                      + (ko + ak8) * 2;
                ldsm_x4(addr, ah[mi][0], ah[mi][1], ah[mi][2], ah[mi][3]);
            }
            #pragma unroll
            for (int ni = 0; ni < 4; ni++) {
                const uint32_t addr = st + TILEB
                                      + (wn + ni * 16 + (lane & 7) + nsub) * PADB
                                      + (ko + bk8) * 2;
                uint32_t r0, r1, r2, r3;
                ldsm_x4(addr, r0, r1, r2, r3);
                wh[ni * 2][0] = r0; wh[ni * 2][1] = r1;
                wh[ni * 2 + 1][0] = r2; wh[ni * 2 + 1][1] = r3;
            }
            #pragma unroll
            for (int mi = 0; mi < 2; mi++)
                #pragma unroll
                for (int nj = 0; nj < 8; nj++)
                    mma16816(acc[mi][nj], ah[mi], wh[nj]);
        }
    }

    if (mode == 0) {
        #pragma unroll
        for (int mi = 0; mi < 2; mi++) {
            const int row = bm + wm + mi * 16 + (lane >> 2);
            #pragma unroll
            for (int nj = 0; nj < 8; nj++) {
                const int col = bn + wn + nj * 8 + (lane & 3) * 2;
                const float b0 = bias[col], b1 = bias[col + 1];
                float2* c0 = (float2*)(C + (size_t)row * N + col);
                float2* c1 = (float2*)(C + (size_t)(row + 8) * N + col);
                *c0 = make_float2(acc[mi][nj][0] + b0, acc[mi][nj][1] + b1);
                *c1 = make_float2(acc[mi][nj][2] + b0, acc[mi][nj][3] + b1);
            }
        }
    } else {
        // QKV epilogue: bias + RoPE + fp16 head-major store
        const int gc = bn + wn;                 // warp col base (multiple of 64)
        const int type = gc >> 10;              // 0=q, 1=k, 2=v
        const int hh = (gc & 1023) >> 6;        // head index
        __half* dstbase = (type == 0) ? g_qh : (type == 1 ? g_kh : g_vh);
        const float qs = (type == 0) ? 0.125f : 1.0f;
        #pragma unroll
        for (int mi = 0; mi < 2; mi++) {
            const int row = bm + wm + mi * 16 + (lane >> 2);
            #pragma unroll
            for (int rr = 0; rr < 2; rr++) {
                const int r = row + rr * 8;
                const int s = r & (Ss - 1);
                const int bidx = r >> 11;
                __half* dst = dstbase + ((size_t)(bidx * Hh + hh) * Ss + s) * HDIM;
                const int ci = rr * 2;
                #pragma unroll
                for (int nj = 0; nj < 4; nj++) {
                    const int j = nj * 8 + 2 * (lane & 3);
                    const float a0 = acc[mi][nj][ci]         + bias[gc + j];
                    const float a1 = acc[mi][nj][ci + 1]     + bias[gc + j + 1];
                    const float b0 = acc[mi][nj + 4][ci]     + bias[gc + j + 32];
                    const float b1 = acc[mi][nj + 4][ci + 1] + bias[gc + j + 33];
                    float o0, o1, o2, o3;
                    if (type == 2) {
                        o0 = a0; o1 = a1; o2 = b0; o3 = b1;
                    } else {
                        const float2 cc = *(const float2*)&g_cos[s * 32 + j];
                        const float2 sn = *(const float2*)&g_sin[s * 32 + j];
                        o0 = (a0 * cc.x - b0 * sn.x) * qs;
                        o1 = (a1 * cc.y - b1 * sn.y) * qs;
                        o2 = (b0 * cc.x + a0 * sn.x) * qs;
                        o3 = (b1 * cc.y + a1 * sn.y) * qs;
                    }
                    *(uint32_t*)(dst + j)      = packf2h(o0, o1);
                    *(uint32_t*)(dst + j + 32) = packf2h(o2, o3);
                }
            }
        }
    }
}

// ---------------------------------------------------------------------------
// Tensor-core flash attention (causal), 64 q-rows per CTA, 128 threads.
// Epilogue writes fp16 y into g_hA.
// ---------------------------------------------------------------------------
#define FROWH 72
#define FROWB (FROWH * 2)
#define FTILE (64 * FROWB)

__global__ void __launch_bounds__(128)
flash_mma_kernel() {
    __shared__ __align__(16) char fsm[5 * FTILE];   // Q | K0 | K1 | V0 | V1
    const int qblk = gridDim.x - 1 - blockIdx.x;    // long CTAs first
    const int bh = blockIdx.y;
    const int tid = threadIdx.x, lane = tid & 31, w = tid >> 5;
    const int qbase = qblk * 64, wm = w * 16;
    const uint32_t sq = smem_to_u32(fsm);
    const uint32_t sk0 = sq + FTILE, sk1 = sq + 2 * FTILE;
    const uint32_t sv0 = sq + 3 * FTILE, sv1 = sq + 4 * FTILE;

    const size_t hb = (size_t)bh * Ss * HDIM;

    {
        const __half* qsrc = g_qh + hb + (size_t)qbase * HDIM;
        #pragma unroll
        for (int i = 0; i < 4; i++) {
            const int c = tid + i * 128;
            const int row = c >> 3, col = (c & 7) * 8;
            CP_ASYNC16(sq + row * FROWB + col * 2, qsrc + row * HDIM + col);
        }
    }
    auto fetch_kv = [&](int kt) {
        const __half* ksrc = g_kh + hb + (size_t)(kt * 64) * HDIM;
        const __half* vsrc = g_vh + hb + (size_t)(kt * 64) * HDIM;
        const uint32_t kb = (kt & 1) ? sk1 : sk0;
        const uint32_t vb = (kt & 1) ? sv1 : sv0;
        #pragma unroll
        for (int i = 0; i < 4; i++) {
            const int c = tid + i * 128;
            const int row = c >> 3, col = (c & 7) * 8;
            CP_ASYNC16(kb + row * FROWB + col * 2, ksrc + row * HDIM + col);
            CP_ASYNC16(vb + row * FROWB + col * 2, vsrc + row * HDIM + col);
        }
    };
    const int nt = qblk + 1;
    fetch_kv(0); CP_COMMIT();
    if (nt > 1) { fetch_kv(1); CP_COMMIT(); }

    uint32_t qf[4][4];
    float o[8][4];
    #pragma unroll
    for (int nj = 0; nj < 8; nj++)
        #pragma unroll
        for (int r = 0; r < 4; r++) o[nj][r] = 0.f;
    float mrow0 = -INFINITY, mrow1 = -INFINITY, lrow0 = 0.f, lrow1 = 0.f;

    for (int kt = 0; kt < nt; kt++) {
        if (kt + 1 < nt) {
            if (kt) { fetch_kv(kt + 1); CP_COMMIT(); }
            CP_WAIT1();
        } else {
            CP_WAIT0();
        }
        __syncthreads();

        if (kt == 0) {
            #pragma unroll
            for (int ks = 0; ks < 4; ks++) {
                const uint32_t addr = sq + (wm + (lane & 15)) * FROWB
                                      + (ks * 16 + (lane >> 4) * 8) * 2;
                ldsm_x4(addr, qf[ks][0], qf[ks][1], qf[ks][2], qf[ks][3]);
            }
        }

        const uint32_t kb = (kt & 1) ? sk1 : sk0;
        const uint32_t vb = (kt & 1) ? sv1 : sv0;

        float s[8][4];
        #pragma unroll
        for (int nj = 0; nj < 8; nj++)
            #pragma unroll
            for (int r = 0; r < 4; r++) s[nj][r] = 0.f;
        const int sel = lane >> 3;
        #pragma unroll
        for (int ks = 0; ks < 4; ks++) {
            #pragma unroll
            for (int np = 0; np < 4; np++) {
                const uint32_t addr = kb
                    + (np * 16 + (lane & 7) + (sel >> 1) * 8) * FROWB
                    + (ks * 16 + (sel & 1) * 8) * 2;
                uint32_t r0, r1, r2, r3;
                ldsm_x4(addr, r0, r1, r2, r3);
                uint32_t b0[2] = {r0, r1}, b1[2] = {r2, r3};
                mma16816(s[np * 2], qf[ks], b0);
                mma16816(s[np * 2 + 1], qf[ks], b1);
            }
        }

        if (kt == qblk) {
            const int lr0 = wm + (lane >> 2), lr1 = lr0 + 8;
            #pragma unroll
            for (int nj = 0; nj < 8; nj++) {
                const int ck = nj * 8 + 2 * (lane & 3);
                if (ck > lr0)     s[nj][0] = -INFINITY;
                if (ck + 1 > lr0) s[nj][1] = -INFINITY;
                if (ck > lr1)     s[nj][2] = -INFINITY;
                if (ck + 1 > lr1) s[nj][3] = -INFINITY;
            }
        }

        float mx0 = -INFINITY, mx1 = -INFINITY;
        #pragma unroll
        for (int nj = 0; nj < 8; nj++) {
            mx0 = fmaxf(mx0, fmaxf(s[nj][0], s[nj][1]));
            mx1 = fmaxf(mx1, fmaxf(s[nj][2], s[nj][3]));
        }
        mx0 = fmaxf(mx0, __shfl_xor_sync(0xffffffffu, mx0, 1));
        mx0 = fmaxf(mx0, __shfl_xor_sync(0xffffffffu, mx0, 2));
        mx1 = fmaxf(mx1, __shfl_xor_sync(0xffffffffu, mx1, 1));
        mx1 = fmaxf(mx1, __shfl_xor_sync(0xffffffffu, mx1, 2));
        const float mn0 = fmaxf(mrow0, mx0), mn1 = fmaxf(mrow1, mx1);
        const float c0 = __expf(mrow0 - mn0), c1 = __expf(mrow1 - mn1);
        float sum0 = 0.f, sum1 = 0.f;
        #pragma unroll
        for (int nj = 0; nj < 8; nj++) {
            s[nj][0] = __expf(s[nj][0] - mn0);
            s[nj][1] = __expf(s[nj][1] - mn0);
            s[nj][2] = __expf(s[nj][2] - mn1);
            s[nj][3] = __expf(s[nj][3] - mn1);
            sum0 += s[nj][0] + s[nj][1];
            sum1 += s[nj][2] + s[nj][3];
        }
        sum0 += __shfl_xor_sync(0xffffffffu, sum0, 1);
        sum0 += __shfl_xor_sync(0xffffffffu, sum0, 2);
        sum1 += __shfl_xor_sync(0xffffffffu, sum1, 1);
        sum1 += __shfl_xor_sync(0xffffffffu, sum1, 2);
        lrow0 = lrow0 * c0 + sum0;
        lrow1 = lrow1 * c1 + sum1;
        #pragma unroll
        for (int nj = 0; nj < 8; nj++) {
            o[nj][0] *= c0; o[nj][1] *= c0;
            o[nj][2] *= c1; o[nj][3] *= c1;
        }
        mrow0 = mn0; mrow1 = mn1;

        #pragma unroll
        for (int ks = 0; ks < 4; ks++) {
            uint32_t a[4];
            a[0] = packf2h(s[2 * ks][0], s[2 * ks][1]);
            a[1] = packf2h(s[2 * ks][2], s[2 * ks][3]);
            a[2] = packf2h(s[2 * ks + 1][0], s[2 * ks + 1][1]);
            a[3] = packf2h(s[2 * ks + 1][2], s[2 * ks + 1][3]);
            #pragma unroll
            for (int np = 0; np < 4; np++) {
                const uint32_t addr = vb
                    + (ks * 16 + (lane & 7) + (lane & 8)) * FROWB
                    + (np * 16 + ((lane >> 4) & 1) * 8) * 2;
                uint32_t r0, r1, r2, r3;
                ldsm_x4t(addr, r0, r1, r2, r3);
                uint32_t b0[2] = {r0, r1}, b1[2] = {r2, r3};
                mma16816(o[np * 2], a, b0);
                mma16816(o[np * 2 + 1], a, b1);
            }
        }
        __syncthreads();
    }

    // epilogue: write fp16 y (input to projection GEMM)
    const float inv0 = 1.f / lrow0, inv1 = 1.f / lrow1;
    const int b = bh >> 4, h = bh & 15;
    const int row0 = qbase + wm + (lane >> 2);
    const size_t y0 = ((size_t)(b * Ss + row0)) * Dd + h * HDIM;
    const size_t y1 = y0 + (size_t)8 * Dd;
    #pragma unroll
    for (int nj = 0; nj < 8; nj++) {
        const int col = nj * 8 + 2 * (lane & 3);
        *(uint32_t*)(g_hA + y0 + col) = packf2h(o[nj][0] * inv0, o[nj][1] * inv0);
        *(uint32_t*)(g_hA + y1 + col) = packf2h(o[nj][2] * inv1, o[nj][3] * inv1);
    }
}

// ---------------------------------------------------------------------------
// Launch: weight splits on side stream; joins placed just before each consumer
// ---------------------------------------------------------------------------
extern "C" void kernel_launch(void* const* d_in, const int* in_sizes, int n_in,
                              void* d_out, int out_size) {
    const float* x      = (const float*)d_in[0];
    const float* norm_w = (const float*)d_in[1];
    const float* qkv_w  = (const float*)d_in[2];
    const float* qkv_b  = (const float*)d_in[3];
    const float* proj_w = (const float*)d_in[4];
    const float* proj_b = (const float*)d_in[5];
    float* out = (float*)d_out;

    __half *p_hA, *p_hW, *p_hWp;
    cudaGetSymbolAddress((void**)&p_hA, g_hA);
    cudaGetSymbolAddress((void**)&p_hW, g_hW);
    cudaGetSymbolAddress((void**)&p_hWp, g_hWp);

    static cudaStream_t s_aux = nullptr;
    static cudaEvent_t ev_fork = nullptr, ev_qkvw = nullptr, ev_projw = nullptr;
    if (s_aux == nullptr) {
        cudaStreamCreateWithFlags(&s_aux, cudaStreamNonBlocking);
        cudaEventCreateWithFlags(&ev_fork, cudaEventDisableTiming);
        cudaEventCreateWithFlags(&ev_qkvw, cudaEventDisableTiming);
        cudaEventCreateWithFlags(&ev_projw, cudaEventDisableTiming);
    }
    cudaFuncSetAttribute(gemm_f16, cudaFuncAttributeMaxDynamicSharedMemorySize, GSMEM);

    // fork: weight conversions on side stream
    cudaEventRecord(ev_fork, 0);
    cudaStreamWaitEvent(s_aux, ev_fork, 0);
    split_f16_hi_kernel<<<(QKVD * Dd / 4 + 255) / 256, 256, 0, s_aux>>>(
        (const float4*)qkv_w, (uint2*)p_hW, QKVD * Dd / 4);
    cudaEventRecord(ev_qkvw, s_aux);
    split_f16_hi_kernel<<<(Dd * Dd / 4 + 255) / 256, 256, 0, s_aux>>>(
        (const float4*)proj_w, (uint2*)p_hWp, Dd * Dd / 4);
    cudaEventRecord(ev_projw, s_aux);

    // main stream: rmsnorm + rope tables (overlap with qkv weight split)
    rmsnorm_h_kernel<<<Mrows, 256>>>(x, norm_w);
    rope_invf_kernel<<<1, 32>>>();
    rope_table_kernel<<<Ss * 32 / 256, 256>>>();

    // join 1: qkv weights ready
    cudaStreamWaitEvent(0, ev_qkvw, 0);
    // QKV GEMM with fused bias+RoPE+fp16 head-major epilogue
    gemm_f16<<<dim3(QKVD / 128, Mrows / 128), 256, GSMEM>>>(
        p_hA, p_hW, qkv_b, out /*unused*/, Mrows, QKVD, Dd, 1);
    // tensor-core flash attention (writes fp16 y into g_hA); proj split overlaps
    flash_mma_kernel<<<dim3(Ss / 64, Bb * Hh), 128>>>();

    // join 2: proj weights ready
    cudaStreamWaitEvent(0, ev_projw, 0);
    // Output projection (plain fp32 epilogue)
    gemm_f16<<<dim3(Dd / 128, Mrows / 128), 256, GSMEM>>>(
        p_hA, p_hWp, proj_b, out, Mrows, Dd, Dd, 0);

    (void)in_sizes; (void)n_in; (void)out_size;
}

// round 16
// speedup vs baseline: 1.0166x; 1.0166x over previous
#include <cuda_runtime.h>
#include <cuda_fp16.h>
#include <cstdint>
#include <math.h>

#define Bb 2
#define Ss 2048
#define Dd 1024
#define Hh 16
#define HDIM 64
#define Mrows (Bb*Ss)   // 4096
#define QKVD (3*Dd)     // 3072

// ---------------------------------------------------------------------------
// Scratch
// ---------------------------------------------------------------------------
__device__ float g_cos[Ss * 32];
__device__ float g_sin[Ss * 32];
__device__ __half g_hA[(size_t)Mrows * Dd];
__device__ __half g_hW[(size_t)QKVD * Dd];   // qkv weights fp16
__device__ __half g_hWp[(size_t)Dd * Dd];    // proj weights fp16
// head-major fp16 q/k/v for attention: [b*16+h][s][64]
__device__ __half g_qh[(size_t)Bb * Hh * Ss * HDIM];
__device__ __half g_kh[(size_t)Bb * Hh * Ss * HDIM];
__device__ __half g_vh[(size_t)Bb * Hh * Ss * HDIM];

// ---------------------------------------------------------------------------
// Helpers
// ---------------------------------------------------------------------------
__device__ __forceinline__ uint32_t smem_to_u32(const void* p) {
    uint32_t a;
    asm("{ .reg .u64 t; cvta.to.shared.u64 t, %1; cvt.u32.u64 %0, t; }"
        : "=r"(a) : "l"(p));
    return a;
}
__device__ __forceinline__ void ldsm_x4(uint32_t addr, uint32_t& r0, uint32_t& r1,
                                        uint32_t& r2, uint32_t& r3) {
    asm volatile("ldmatrix.sync.aligned.m8n8.x4.shared.b16 {%0,%1,%2,%3}, [%4];"
                 : "=r"(r0), "=r"(r1), "=r"(r2), "=r"(r3) : "r"(addr));
}
__device__ __forceinline__ void ldsm_x4t(uint32_t addr, uint32_t& r0, uint32_t& r1,
                                         uint32_t& r2, uint32_t& r3) {
    asm volatile("ldmatrix.sync.aligned.m8n8.x4.trans.shared.b16 {%0,%1,%2,%3}, [%4];"
                 : "=r"(r0), "=r"(r1), "=r"(r2), "=r"(r3) : "r"(addr));
}
__device__ __forceinline__ void mma16816(float* c, const uint32_t* a, const uint32_t* b) {
    asm volatile("mma.sync.aligned.m16n8k16.row.col.f32.f16.f16.f32 "
                 "{%0,%1,%2,%3}, {%4,%5,%6,%7}, {%8,%9}, {%0,%1,%2,%3};"
                 : "+f"(c[0]), "+f"(c[1]), "+f"(c[2]), "+f"(c[3])
                 : "r"(a[0]), "r"(a[1]), "r"(a[2]), "r"(a[3]), "r"(b[0]), "r"(b[1]));
}
#define CP_ASYNC16(sa, ga) \
    asm volatile("cp.async.cg.shared.global [%0], [%1], 16;" :: "r"(sa), "l"(ga))
#define CP_COMMIT() asm volatile("cp.async.commit_group;" ::: "memory")
#define CP_WAIT1()  asm volatile("cp.async.wait_group 1;" ::: "memory")
#define CP_WAIT0()  asm volatile("cp.async.wait_group 0;" ::: "memory")

__device__ __forceinline__ uint32_t packf2h(float a, float b) {
    __half2 h = __floats2half2_rn(a, b);
    return *(uint32_t*)&h;
}
__device__ __forceinline__ uint32_t packh(__half a, __half b) {
    return ((uint32_t)__half_as_ushort(b) << 16) | (uint32_t)__half_as_ushort(a);
}

// ---------------------------------------------------------------------------
// Fused RMSNorm + fp16 convert: x -> g_hA
// ---------------------------------------------------------------------------
__global__ void __launch_bounds__(256)
rmsnorm_h_kernel(const float* __restrict__ x, const float* __restrict__ w) {
    const int row = blockIdx.x;
    const float4* xr = (const float4*)(x + (size_t)row * Dd);
    const float4 v = xr[threadIdx.x];
    float ss = v.x * v.x + v.y * v.y + v.z * v.z + v.w * v.w;
    __shared__ float red[8];
    #pragma unroll
    for (int o = 16; o > 0; o >>= 1) ss += __shfl_xor_sync(0xffffffffu, ss, o);
    const int wid = threadIdx.x >> 5, lid = threadIdx.x & 31;
    if (lid == 0) red[wid] = ss;
    __syncthreads();
    if (wid == 0) {
        ss = (lid < 8) ? red[lid] : 0.f;
        #pragma unroll
        for (int o = 4; o > 0; o >>= 1) ss += __shfl_xor_sync(0xffffffffu, ss, o);
        if (lid == 0) red[0] = ss;
    }
    __syncthreads();
    const float inv = rsqrtf(red[0] * (1.0f / Dd) + 1e-6f);
    const float4 wv = ((const float4*)w)[threadIdx.x];
    const size_t o4 = (size_t)row * (Dd / 4) + threadIdx.x;
    ((uint2*)g_hA)[o4] = make_uint2(
        packh(__float2half_rn(v.x * inv * wv.x), __float2half_rn(v.y * inv * wv.y)),
        packh(__float2half_rn(v.z * inv * wv.z), __float2half_rn(v.w * inv * wv.w)));
}

// ---------------------------------------------------------------------------
// RoPE table: inv_freq[i] = r^i (r = 10^-0.125, fp64 literal; binary powers),
// fp64 range reduction + fp32 sincosf. No fp64 transcendentals.
// ---------------------------------------------------------------------------
__global__ void __launch_bounds__(256)
rope_table_kernel() {
    __shared__ double sinv[32];
    if (threadIdx.x < 32) {
        const int i = threadIdx.x;
        const double r1 = 0.7498942093324559;     // 10^(-4/32)
        const double r2 = r1 * r1;
        const double r4 = r2 * r2;
        const double r8 = r4 * r4;
        const double r16 = r8 * r8;
        double v = 1.0;
        if (i & 1) v *= r1;
        if (i & 2) v *= r2;
        if (i & 4) v *= r4;
        if (i & 8) v *= r8;
        if (i & 16) v *= r16;
        sinv[i] = v;
    }
    __syncthreads();
    const int idx = blockIdx.x * blockDim.x + threadIdx.x;  // 0..65535
    const int t = idx >> 5, i = idx & 31;
    const double TWO_PI = 6.283185307179586476925286766559;
    double a = (double)t * sinv[i];
    double r = a - rint(a * (1.0 / TWO_PI)) * TWO_PI;   // |r| <= pi
    float c, s;
    sincosf((float)r, &s, &c);
    g_cos[t * 32 + i] = c;
    g_sin[t * 32 + i] = s;
}

// ---------------------------------------------------------------------------
// fp32 -> fp16 (weights)
// ---------------------------------------------------------------------------
__global__ void split_f16_hi_kernel(const float4* __restrict__ src,
                                    uint2* __restrict__ hi, int n4) {
    int i = blockIdx.x * blockDim.x + threadIdx.x;
    if (i >= n4) return;
    float4 v = src[i];
    hi[i] = make_uint2(packh(__float2half_rn(v.x), __float2half_rn(v.y)),
                       packh(__float2half_rn(v.z), __float2half_rn(v.w)));
}

// ---------------------------------------------------------------------------
// Single-pass fp16 GEMM via mma.sync: C = A * W^T + bias
//   CTA 128x128, 8 warps (4M x 2N), KC=64, 3-stage cp.async pipeline.
//   mode 0: fp32 C (+bias).  mode 1: QKV epilogue (bias+RoPE+fp16 head-major).
// ---------------------------------------------------------------------------
#define PADB  144                    // 64 halfs (128 B) + 16 pad
#define TILEB (128 * PADB)           // 18432
#define STAGEB (2 * TILEB)           // 36864: A, W
#define NSTAGE 3
#define GSMEM (NSTAGE * STAGEB)      // 110592

__global__ void __launch_bounds__(256)
gemm_f16(const __half* __restrict__ Ahi, const __half* __restrict__ Whi,
         const float* __restrict__ bias, float* __restrict__ C,
         int M, int N, int K, int mode) {
    extern __shared__ char smem[];
    const uint32_t sb = smem_to_u32(smem);
    const int tid = threadIdx.x, lane = tid & 31, w = tid >> 5;
    const int bm = blockIdx.y * 128, bn = blockIdx.x * 128;
    const int wm = (w >> 1) * 32, wn = (w & 1) * 64;

    auto load_stage = [&](int s, int k0) {
        const uint32_t st = sb + s * STAGEB;
        #pragma unroll
        for (int t = 0; t < 2; t++) {
            const __half* src = (t == 0 ? Ahi : Whi)
                                + (size_t)(t == 0 ? bm : bn) * K + k0;
            const uint32_t tb = st + t * TILEB;
            #pragma unroll
            for (int j = 0; j < 4; j++) {
                const int c = tid + j * 256;
                const int row = c >> 3, c16 = c & 7;
                CP_ASYNC16(tb + row * PADB + c16 * 16,
                           src + (size_t)row * K + c16 * 8);
            }
        }
    };

    float acc[2][8][4];
    #pragma unroll
    for (int mi = 0; mi < 2; mi++)
        #pragma unroll
        for (int nj = 0; nj < 8; nj++)
            #pragma unroll
            for (int r = 0; r < 4; r++) acc[mi][nj][r] = 0.f;

    load_stage(0, 0);  CP_COMMIT();
    load_stage(1, 64); CP_COMMIT();

    const int nch = K >> 6;          // chunks of 64
    const int sel = lane >> 3;
    const int asub = (sel & 1) * 8, ak8 = (sel >> 1) * 8;
    const int nsub = (sel >> 1) * 8, bk8 = (sel & 1) * 8;

    for (int cidx = 0; cidx < nch; cidx++) {
        CP_WAIT1();
        __syncthreads();
        if (cidx + 2 < nch) load_stage((cidx + 2) % NSTAGE, (cidx + 2) * 64);
        CP_COMMIT();

        const uint32_t st = sb + (cidx % NSTAGE) * STAGEB;
        #pragma unroll
        for (int kk = 0; kk < 4; kk++) {
            const int ko = kk * 16;
            uint32_t ah[2][4], wh[8][2];
            #pragma unroll
            for (int mi = 0; mi < 2; mi++) {
                const uint32_t addr = st + (wm + mi * 16 + (lane & 7) + asub) * PADB
                                      + (ko + ak8) * 2;
                ldsm_x4(addr, ah[mi][0], ah[mi][1], ah[mi][2], ah[mi][3]);
            }
            #pragma unroll
            for (int ni = 0; ni < 4; ni++) {
                const uint32_t addr = st + TILEB
                                      + (wn + ni * 16 + (lane & 7) + nsub) * PADB
                                      + (ko + bk8) * 2;
                uint32_t r0, r1, r2, r3;
                ldsm_x4(addr, r0, r1, r2, r3);
                wh[ni * 2][0] = r0; wh[ni * 2][1] = r1;
                wh[ni * 2 + 1][0] = r2; wh[ni * 2 + 1][1] = r3;
            }
            #pragma unroll
            for (int mi = 0; mi < 2; mi++)
                #pragma unroll
                for (int nj = 0; nj < 8; nj++)
                    mma16816(acc[mi][nj], ah[mi], wh[nj]);
        }
    }

    if (mode == 0) {
        #pragma unroll
        for (int mi = 0; mi < 2; mi++) {
            const int row = bm + wm + mi * 16 + (lane >> 2);
            #pragma unroll
            for (int nj = 0; nj < 8; nj++) {
                const int col = bn + wn + nj * 8 + (lane & 3) * 2;
                const float b0 = bias[col], b1 = bias[col + 1];
                float2* c0 = (float2*)(C + (size_t)row * N + col);
                float2* c1 = (float2*)(C + (size_t)(row + 8) * N + col);
                *c0 = make_float2(acc[mi][nj][0] + b0, acc[mi][nj][1] + b1);
                *c1 = make_float2(acc[mi][nj][2] + b0, acc[mi][nj][3] + b1);
            }
        }
    } else {
        // QKV epilogue: bias + RoPE + fp16 head-major store
        const int gc = bn + wn;                 // warp col base (multiple of 64)
        const int type = gc >> 10;              // 0=q, 1=k, 2=v
        const int hh = (gc & 1023) >> 6;        // head index
        __half* dstbase = (type == 0) ? g_qh : (type == 1 ? g_kh : g_vh);
        const float qs = (type == 0) ? 0.125f : 1.0f;
        #pragma unroll
        for (int mi = 0; mi < 2; mi++) {
            const int row = bm + wm + mi * 16 + (lane >> 2);
            #pragma unroll
            for (int rr = 0; rr < 2; rr++) {
                const int r = row + rr * 8;
                const int s = r & (Ss - 1);
                const int bidx = r >> 11;
                __half* dst = dstbase + ((size_t)(bidx * Hh + hh) * Ss + s) * HDIM;
                const int ci = rr * 2;
                #pragma unroll
                for (int nj = 0; nj < 4; nj++) {
                    const int j = nj * 8 + 2 * (lane & 3);
                    const float a0 = acc[mi][nj][ci]         + bias[gc + j];
                    const float a1 = acc[mi][nj][ci + 1]     + bias[gc + j + 1];
                    const float b0 = acc[mi][nj + 4][ci]     + bias[gc + j + 32];
                    const float b1 = acc[mi][nj + 4][ci + 1] + bias[gc + j + 33];
                    float o0, o1, o2, o3;
                    if (type == 2) {
                        o0 = a0; o1 = a1; o2 = b0; o3 = b1;
                    } else {
                        const float2 cc = *(const float2*)&g_cos[s * 32 + j];
                        const float2 sn = *(const float2*)&g_sin[s * 32 + j];
                        o0 = (a0 * cc.x - b0 * sn.x) * qs;
                        o1 = (a1 * cc.y - b1 * sn.y) * qs;
                        o2 = (b0 * cc.x + a0 * sn.x) * qs;
                        o3 = (b1 * cc.y + a1 * sn.y) * qs;
                    }
                    *(uint32_t*)(dst + j)      = packf2h(o0, o1);
                    *(uint32_t*)(dst + j + 32) = packf2h(o2, o3);
                }
            }
        }
    }
}

// ---------------------------------------------------------------------------
// Tensor-core flash attention (causal), 64 q-rows per CTA, 128 threads.
// Epilogue writes fp16 y into g_hA.
// ---------------------------------------------------------------------------
#define FROWH 72
#define FROWB (FROWH * 2)
#define FTILE (64 * FROWB)

__global__ void __launch_bounds__(128)
flash_mma_kernel() {
    __shared__ __align__(16) char fsm[5 * FTILE];   // Q | K0 | K1 | V0 | V1
    const int qblk = gridDim.x - 1 - blockIdx.x;    // long CTAs first
    const int bh = blockIdx.y;
    const int tid = threadIdx.x, lane = tid & 31, w = tid >> 5;
    const int qbase = qblk * 64, wm = w * 16;
    const uint32_t sq = smem_to_u32(fsm);
    const uint32_t sk0 = sq + FTILE, sk1 = sq + 2 * FTILE;
    const uint32_t sv0 = sq + 3 * FTILE, sv1 = sq + 4 * FTILE;

    const size_t hb = (size_t)bh * Ss * HDIM;

    {
        const __half* qsrc = g_qh + hb + (size_t)qbase * HDIM;
        #pragma unroll
        for (int i = 0; i < 4; i++) {
            const int c = tid + i * 128;
            const int row = c >> 3, col = (c & 7) * 8;
            CP_ASYNC16(sq + row * FROWB + col * 2, qsrc + row * HDIM + col);
        }
    }
    auto fetch_kv = [&](int kt) {
        const __half* ksrc = g_kh + hb + (size_t)(kt * 64) * HDIM;
        const __half* vsrc = g_vh + hb + (size_t)(kt * 64) * HDIM;
        const uint32_t kb = (kt & 1) ? sk1 : sk0;
        const uint32_t vb = (kt & 1) ? sv1 : sv0;
        #pragma unroll
        for (int i = 0; i < 4; i++) {
            const int c = tid + i * 128;
            const int row = c >> 3, col = (c & 7) * 8;
            CP_ASYNC16(kb + row * FROWB + col * 2, ksrc + row * HDIM + col);
            CP_ASYNC16(vb + row * FROWB + col * 2, vsrc + row * HDIM + col);
        }
    };
    const int nt = qblk + 1;
    fetch_kv(0); CP_COMMIT();
    if (nt > 1) { fetch_kv(1); CP_COMMIT(); }

    uint32_t qf[4][4];
    float o[8][4];
    #pragma unroll
    for (int nj = 0; nj < 8; nj++)
        #pragma unroll
        for (int r = 0; r < 4; r++) o[nj][r] = 0.f;
    float mrow0 = -INFINITY, mrow1 = -INFINITY, lrow0 = 0.f, lrow1 = 0.f;

    for (int kt = 0; kt < nt; kt++) {
        if (kt + 1 < nt) {
            if (kt) { fetch_kv(kt + 1); CP_COMMIT(); }
            CP_WAIT1();
        } else {
            CP_WAIT0();
        }
        __syncthreads();

        if (kt == 0) {
            #pragma unroll
            for (int ks = 0; ks < 4; ks++) {
                const uint32_t addr = sq + (wm + (lane & 15)) * FROWB
                                      + (ks * 16 + (lane >> 4) * 8) * 2;
                ldsm_x4(addr, qf[ks][0], qf[ks][1], qf[ks][2], qf[ks][3]);
            }
        }

        const uint32_t kb = (kt & 1) ? sk1 : sk0;
        const uint32_t vb = (kt & 1) ? sv1 : sv0;

        float s[8][4];
        #pragma unroll
        for (int nj = 0; nj < 8; nj++)
            #pragma unroll
            for (int r = 0; r < 4; r++) s[nj][r] = 0.f;
        const int sel = lane >> 3;
        #pragma unroll
        for (int ks = 0; ks < 4; ks++) {
            #pragma unroll
            for (int np = 0; np < 4; np++) {
                const uint32_t addr = kb
                    + (np * 16 + (lane & 7) + (sel >> 1) * 8) * FROWB
                    + (ks * 16 + (sel & 1) * 8) * 2;
                uint32_t r0, r1, r2, r3;
                ldsm_x4(addr, r0, r1, r2, r3);
                uint32_t b0[2] = {r0, r1}, b1[2] = {r2, r3};
                mma16816(s[np * 2], qf[ks], b0);
                mma16816(s[np * 2 + 1], qf[ks], b1);
            }
        }

        if (kt == qblk) {
            const int lr0 = wm + (lane >> 2), lr1 = lr0 + 8;
            #pragma unroll
            for (int nj = 0; nj < 8; nj++) {
                const int ck = nj * 8 + 2 * (lane & 3);
                if (ck > lr0)     s[nj][0] = -INFINITY;
                if (ck + 1 > lr0) s[nj][1] = -INFINITY;
                if (ck > lr1)     s[nj][2] = -INFINITY;
                if (ck + 1 > lr1) s[nj][3] = -INFINITY;
            }
        }

        float mx0 = -INFINITY, mx1 = -INFINITY;
        #pragma unroll
        for (int nj = 0; nj < 8; nj++) {
            mx0 = fmaxf(mx0, fmaxf(s[nj][0], s[nj][1]));
            mx1 = fmaxf(mx1, fmaxf(s[nj][2], s[nj][3]));
        }
        mx0 = fmaxf(mx0, __shfl_xor_sync(0xffffffffu, mx0, 1));
        mx0 = fmaxf(mx0, __shfl_xor_sync(0xffffffffu, mx0, 2));
        mx1 = fmaxf(mx1, __shfl_xor_sync(0xffffffffu, mx1, 1));
        mx1 = fmaxf(mx1, __shfl_xor_sync(0xffffffffu, mx1, 2));
        const float mn0 = fmaxf(mrow0, mx0), mn1 = fmaxf(mrow1, mx1);
        const float c0 = __expf(mrow0 - mn0), c1 = __expf(mrow1 - mn1);
        float sum0 = 0.f, sum1 = 0.f;
        #pragma unroll
        for (int nj = 0; nj < 8; nj++) {
            s[nj][0] = __expf(s[nj][0] - mn0);
            s[nj][1] = __expf(s[nj][1] - mn0);
            s[nj][2] = __expf(s[nj][2] - mn1);
            s[nj][3] = __expf(s[nj][3] - mn1);
            sum0 += s[nj][0] + s[nj][1];
            sum1 += s[nj][2] + s[nj][3];
        }
        sum0 += __shfl_xor_sync(0xffffffffu, sum0, 1);
        sum0 += __shfl_xor_sync(0xffffffffu, sum0, 2);
        sum1 += __shfl_xor_sync(0xffffffffu, sum1, 1);
        sum1 += __shfl_xor_sync(0xffffffffu, sum1, 2);
        lrow0 = lrow0 * c0 + sum0;
        lrow1 = lrow1 * c1 + sum1;
        #pragma unroll
        for (int nj = 0; nj < 8; nj++) {
            o[nj][0] *= c0; o[nj][1] *= c0;
            o[nj][2] *= c1; o[nj][3] *= c1;
        }
        mrow0 = mn0; mrow1 = mn1;

        #pragma unroll
        for (int ks = 0; ks < 4; ks++) {
            uint32_t a[4];
            a[0] = packf2h(s[2 * ks][0], s[2 * ks][1]);
            a[1] = packf2h(s[2 * ks][2], s[2 * ks][3]);
            a[2] = packf2h(s[2 * ks + 1][0], s[2 * ks + 1][1]);
            a[3] = packf2h(s[2 * ks + 1][2], s[2 * ks + 1][3]);
            #pragma unroll
            for (int np = 0; np < 4; np++) {
                const uint32_t addr = vb
                    + (ks * 16 + (lane & 7) + (lane & 8)) * FROWB
                    + (np * 16 + ((lane >> 4) & 1) * 8) * 2;
                uint32_t r0, r1, r2, r3;
                ldsm_x4t(addr, r0, r1, r2, r3);
                uint32_t b0[2] = {r0, r1}, b1[2] = {r2, r3};
                mma16816(o[np * 2], a, b0);
                mma16816(o[np * 2 + 1], a, b1);
            }
        }
        __syncthreads();
    }

    // epilogue: write fp16 y (input to projection GEMM)
    const float inv0 = 1.f / lrow0, inv1 = 1.f / lrow1;
    const int b = bh >> 4, h = bh & 15;
    const int row0 = qbase + wm + (lane >> 2);
    const size_t y0 = ((size_t)(b * Ss + row0)) * Dd + h * HDIM;
    const size_t y1 = y0 + (size_t)8 * Dd;
    #pragma unroll
    for (int nj = 0; nj < 8; nj++) {
        const int col = nj * 8 + 2 * (lane & 3);
        *(uint32_t*)(g_hA + y0 + col) = packf2h(o[nj][0] * inv0, o[nj][1] * inv0);
        *(uint32_t*)(g_hA + y1 + col) = packf2h(o[nj][2] * inv1, o[nj][3] * inv1);
    }
}

// ---------------------------------------------------------------------------
// Launch (serial stream 0)
// ---------------------------------------------------------------------------
extern "C" void kernel_launch(void* const* d_in, const int* in_sizes, int n_in,
                              void* d_out, int out_size) {
    const float* x      = (const float*)d_in[0];
    const float* norm_w = (const float*)d_in[1];
    const float* qkv_w  = (const float*)d_in[2];
    const float* qkv_b  = (const float*)d_in[3];
    const float* proj_w = (const float*)d_in[4];
    const float* proj_b = (const float*)d_in[5];
    float* out = (float*)d_out;

    __half *p_hA, *p_hW, *p_hWp;
    cudaGetSymbolAddress((void**)&p_hA, g_hA);
    cudaGetSymbolAddress((void**)&p_hW, g_hW);
    cudaGetSymbolAddress((void**)&p_hWp, g_hWp);

    cudaFuncSetAttribute(gemm_f16, cudaFuncAttributeMaxDynamicSharedMemorySize, GSMEM);

    // 1) fused RMSNorm + fp16 convert -> g_hA
    rmsnorm_h_kernel<<<Mrows, 256>>>(x, norm_w);
    // 2) RoPE table (inline inv_freq, no fp64 transcendentals)
    rope_table_kernel<<<Ss * 32 / 256, 256>>>();
    // 3) qkv weights -> fp16
    split_f16_hi_kernel<<<(QKVD * Dd / 4 + 255) / 256, 256>>>(
        (const float4*)qkv_w, (uint2*)p_hW, QKVD * Dd / 4);
    // 4) QKV GEMM with fused bias+RoPE+fp16 head-major epilogue
    gemm_f16<<<dim3(QKVD / 128, Mrows / 128), 256, GSMEM>>>(
        p_hA, p_hW, qkv_b, out /*unused*/, Mrows, QKVD, Dd, 1);
    // 5) tensor-core flash attention (writes fp16 y into g_hA)
    flash_mma_kernel<<<dim3(Ss / 64, Bb * Hh), 128>>>();
    // 6) proj weights -> fp16
    split_f16_hi_kernel<<<(Dd * Dd / 4 + 255) / 256, 256>>>(
        (const float4*)proj_w, (uint2*)p_hWp, Dd * Dd / 4);
    // 7) Output projection (plain fp32 epilogue)
    gemm_f16<<<dim3(Dd / 128, Mrows / 128), 256, GSMEM>>>(
        p_hA, p_hWp, proj_b, out, Mrows, Dd, Dd, 0);

    (void)in_sizes; (void)n_in; (void)out_size;
}